// round 15
// baseline (speedup 1.0000x reference)
#include <cuda_runtime.h>
#include <cuda_fp16.h>
#include <cstdint>

constexpr int NND = 100000;
constexpr int DD  = 128;
constexpr int EE  = 250000;
constexpr int NRL = 16;
constexpr int RR  = 8;
constexpr int H   = 256;
constexpr int TE  = 64;
constexpr int CHUNK = 16;
constexpr int EDGE_GRID = 444;

// Static device scratch
__device__ __half g_Mh[NRL * DD * DD];
__device__ float  g_out[(size_t)NND * DD];
__device__ __half g_xh[(size_t)NND * DD];
__device__ __half g_W1h[H * DD];
__device__ __half g_W2h[H * H];
__device__ __half g_W3h[DD * H];
__device__ int    g_eidsb[(size_t)NRL * EE];
__device__ int    g_fill[NRL];

// ---------------------------------------------------------------------------
__device__ __forceinline__ uint32_t smem_u32(const void* p) {
    return (uint32_t)__cvta_generic_to_shared(p);
}
__device__ __forceinline__ void ldsm4(uint32_t* r, uint32_t addr) {
    asm volatile("ldmatrix.sync.aligned.m8n8.x4.shared.b16 {%0,%1,%2,%3}, [%4];"
                 : "=r"(r[0]), "=r"(r[1]), "=r"(r[2]), "=r"(r[3]) : "r"(addr));
}
__device__ __forceinline__ void mma16(float* d, const uint32_t* a, uint32_t b0, uint32_t b1) {
    asm volatile(
        "mma.sync.aligned.m16n8k16.row.col.f32.f16.f16.f32 "
        "{%0,%1,%2,%3},{%4,%5,%6,%7},{%8,%9},{%0,%1,%2,%3};"
        : "+f"(d[0]), "+f"(d[1]), "+f"(d[2]), "+f"(d[3])
        : "r"(a[0]), "r"(a[1]), "r"(a[2]), "r"(a[3]), "r"(b0), "r"(b1));
}
__device__ __forceinline__ void pack8h(uint32_t* o, const float* f) {
#pragma unroll
    for (int i = 0; i < 4; i++) {
        __half2 h = __floats2half2_rn(f[2 * i], f[2 * i + 1]);
        o[i] = *(uint32_t*)&h;
    }
}

// ---------------------------------------------------------------------------
// Fused prep: build_M | init_out+cvt_x (2 float4/thread) | cvt_w | scatter.
constexpr int PREP_INIT0 = NRL;                       // 16
constexpr int PREP_NCPY  = 6250;                      // 3.2M float4 / 512 per block
constexpr int PREP_CVTW0 = PREP_INIT0 + PREP_NCPY;    // 6266
constexpr int PREP_SCAT0 = PREP_CVTW0 + 256;          // 6522
constexpr int PREP_GRID  = PREP_SCAT0 + 977;          // 7499

__global__ void __launch_bounds__(256) k_prep(const float* __restrict__ x,
                                              const float* __restrict__ eps,
                                              const float* __restrict__ W,
                                              const float* __restrict__ A_emb,
                                              const float* __restrict__ B_emb,
                                              const float* __restrict__ W1,
                                              const float* __restrict__ W2,
                                              const float* __restrict__ W3,
                                              const int* __restrict__ et) {
    int b = blockIdx.x;
    if (b < PREP_INIT0) {
        int t = b;
        __shared__ float As[DD * RR];
        __shared__ float Bs[DD * RR];
        for (int i = threadIdx.x; i < DD * RR; i += blockDim.x) {
            As[i] = A_emb[(size_t)t * DD * RR + i];
            Bs[i] = B_emb[(size_t)t * DD * RR + i];
        }
        __syncthreads();
        for (int idx = threadIdx.x; idx < DD * DD; idx += blockDim.x) {
            int o = idx >> 7;
            int i = idx & 127;
            float s = W[o * DD + i];
#pragma unroll
            for (int k = 0; k < RR; k++) s += Bs[i * RR + k] * As[o * RR + k];
            g_Mh[t * DD * DD + o * DD + i] = __float2half_rn(s);
        }
    } else if (b < PREP_CVTW0) {
        // read x once, 2 independent float4 per thread (MLP=2)
        float s = 1.0f + eps[0];
        int base = (b - PREP_INIT0) * 512 + threadIdx.x;
        int i0 = base, i1 = base + 256;
        float4 v0 = ((const float4*)x)[i0];
        float4 v1 = ((const float4*)x)[i1];
        {
            __half2 h0 = __floats2half2_rn(v0.x, v0.y);
            __half2 h1 = __floats2half2_rn(v0.z, v0.w);
            uint2 u; u.x = *(uint32_t*)&h0; u.y = *(uint32_t*)&h1;
            ((uint2*)g_xh)[i0] = u;
        }
        {
            __half2 h0 = __floats2half2_rn(v1.x, v1.y);
            __half2 h1 = __floats2half2_rn(v1.z, v1.w);
            uint2 u; u.x = *(uint32_t*)&h0; u.y = *(uint32_t*)&h1;
            ((uint2*)g_xh)[i1] = u;
        }
        v0.x *= s; v0.y *= s; v0.z *= s; v0.w *= s;
        v1.x *= s; v1.y *= s; v1.z *= s; v1.w *= s;
        ((float4*)g_out)[i0] = v0;
        ((float4*)g_out)[i1] = v1;
    } else if (b < PREP_SCAT0) {
        int i = (b - PREP_CVTW0) * 256 + threadIdx.x;
        if (i < H * DD) g_W1h[i] = __float2half_rn(W1[i]);
        if (i < H * H)  g_W2h[i] = __float2half_rn(W2[i]);
        if (i < DD * H) g_W3h[i] = __float2half_rn(W3[i]);
    } else {
        __shared__ int lc[NRL], lbase[NRL], lfill[NRL];
        if (threadIdx.x < NRL) { lc[threadIdx.x] = 0; lfill[threadIdx.x] = 0; }
        __syncthreads();
        int e = (b - PREP_SCAT0) * 256 + threadIdx.x;
        int t = -1;
        if (e < EE) {
            t = et[e];
            if (t >= 0 && t < NRL) atomicAdd(&lc[t], 1); else t = -1;
        }
        __syncthreads();
        if (threadIdx.x < NRL && lc[threadIdx.x])
            lbase[threadIdx.x] = atomicAdd(&g_fill[threadIdx.x], lc[threadIdx.x]);
        __syncthreads();
        if (t >= 0) {
            int p = atomicAdd(&lfill[t], 1);
            g_eidsb[(size_t)t * EE + lbase[t] + p] = e;
        }
    }
}

// ---------------------------------------------------------------------------
// Persistent edge GEMM; scatter via lane-paired red.v4. (unchanged from R14)
constexpr int EDGE_SMEM = 32768 + 32768 + CHUNK * TE * 2 * 4;

__global__ void __launch_bounds__(256, 3) k_edge_mma(const __half* __restrict__ xh,
                                                     const int* __restrict__ ei) {
    extern __shared__ char smc[];
    __half* Ms = (__half*)smc;
    char* Xb = smc + 32768;
    int* srcsA = (int*)(smc + 65536);
    int* dstsA = srcsA + CHUNK * TE;
    __shared__ int s_cnt[NRL];
    __shared__ int s_tstart[NRL + 1];
    __shared__ int s_trel[CHUNK];
    int tid = threadIdx.x;

    if (tid < NRL) s_cnt[tid] = g_fill[tid];
    __syncthreads();
    if (tid == 0) {
        int tb = 0;
        for (int t = 0; t < NRL; t++) { s_tstart[t] = tb; tb += (s_cnt[t] + TE - 1) / TE; }
        s_tstart[NRL] = tb;
    }
    __syncthreads();
    int nt = s_tstart[NRL];

    int per = (nt + gridDim.x - 1) / gridDim.x;
    int i0 = blockIdx.x * per;
    int i1 = min(i0 + per, nt);
    if (i0 >= i1) return;

    int lane = tid & 31, w = tid >> 5;
    int wm = w & 1, wn = w >> 1;
    int arow0 = wm * 32 + (lane & 15);
    int brow0 = wn * 32 + (lane & 15);
    uint32_t ms_base = smem_u32(Ms);
    int cur_rel = -1;
    int hi = lane & 1;
    int ocb4 = wn * 32 + ((lane & 3) >> 1) * 4;

    auto gather = [&](int k) {
        char* xb = Xb + (k & 1) * 16384;
        const int* sp = srcsA + k * TE;
        uint32_t xb32 = smem_u32(xb);
#pragma unroll
        for (int i = 0; i < 4; i++) {
            int l = tid + i * 256;
            int r = l >> 4, u = l & 15;
            int s = sp[r];
            bool pa = s >= 0;
            const __half* src = pa ? (xh + (size_t)s * DD + u * 8) : xh;
            uint32_t dst = xb32 + (uint32_t)((r * 16 + (u ^ (r & 7))) * 16);
            asm volatile("cp.async.ca.shared.global [%0], [%1], 16, %2;"
                         :: "r"(dst), "l"(src), "r"(pa ? 16 : 0));
        }
        asm volatile("cp.async.commit_group;");
    };

    for (int gbase = i0; gbase < i1; gbase += CHUNK) {
        int gc = min(CHUNK, i1 - gbase);

        if (tid < gc) {
            int ti = gbase + tid;
            int t = 0;
            for (int tt = 0; tt < NRL; tt++)
                if (ti >= s_tstart[tt] && ti < s_tstart[tt + 1]) t = tt;
            s_trel[tid] = t;
        }
        __syncthreads();

        for (int l = tid; l < gc * TE; l += 256) {
            int k = l >> 6, j = l & 63;
            int t = s_trel[k];
            int row0 = (gbase + k - s_tstart[t]) * TE;
            int cnt = s_cnt[t] - row0;
            int s = -1, d = -1;
            if (j < cnt) {
                int e = g_eidsb[(size_t)t * EE + row0 + j];
                s = ei[e];
                d = ei[EE + e];
                if (s < 0 || s >= NND) s = -1;
                if (d < 0 || d >= NND) d = -1;
            }
            srcsA[l] = s;
            dstsA[l] = d;
        }
        __syncthreads();

        gather(0);
        for (int k = 0; k < gc; k++) {
            if (k + 1 < gc) {
                gather(k + 1);
                asm volatile("cp.async.wait_group 1;");
            } else {
                asm volatile("cp.async.wait_group 0;");
            }
            __syncthreads();

            int t = s_trel[k];
            if (t != cur_rel) {
                const uint4* Msrc = (const uint4*)(g_Mh + (size_t)t * DD * DD);
#pragma unroll
                for (int j = 0; j < 8; j++) {
                    int l = tid + j * 256;
                    int r = l >> 4, u = l & 15;
                    uint4 v = Msrc[l];
                    *(uint4*)((char*)Ms + (r * 16 + (u ^ (r & 7))) * 16) = v;
                }
                cur_rel = t;
                __syncthreads();
            }

            uint32_t xs_base = smem_u32(Xb + (k & 1) * 16384);
            float d[2][4][4];
#pragma unroll
            for (int mi = 0; mi < 2; mi++)
#pragma unroll
                for (int ni = 0; ni < 4; ni++)
#pragma unroll
                    for (int c = 0; c < 4; c++) d[mi][ni][c] = 0.f;

#pragma unroll
            for (int ks = 0; ks < 8; ks++) {
                int uu = ks * 2 + (lane >> 4);
                uint32_t a[2][4], b[2][4];
#pragma unroll
                for (int mi = 0; mi < 2; mi++) {
                    int r = arow0 + mi * 16;
                    ldsm4(a[mi], xs_base + (uint32_t)((r * 16 + (uu ^ (r & 7))) * 16));
                }
#pragma unroll
                for (int pp = 0; pp < 2; pp++) {
                    int r = brow0 + pp * 16;
                    ldsm4(b[pp], ms_base + (uint32_t)((r * 16 + (uu ^ (r & 7))) * 16));
                }
#pragma unroll
                for (int mi = 0; mi < 2; mi++)
#pragma unroll
                    for (int ni = 0; ni < 4; ni++) {
                        int pp = ni >> 1, o = ni & 1;
                        mma16(d[mi][ni], a[mi], b[pp][o], b[pp][2 + o]);
                    }
            }

            const int* dp = dstsA + k * TE;
#pragma unroll
            for (int mi = 0; mi < 2; mi++) {
                int er = wm * 32 + mi * 16 + (lane >> 2);
                int drow = hi ? dp[er + 8] : dp[er];
#pragma unroll
                for (int ni = 0; ni < 4; ni++) {
                    float s0 = hi ? d[mi][ni][0] : d[mi][ni][2];
                    float s1 = hi ? d[mi][ni][1] : d[mi][ni][3];
                    float r0 = __shfl_xor_sync(0xffffffffu, s0, 1);
                    float r1 = __shfl_xor_sync(0xffffffffu, s1, 1);
                    float v0, v1, v2, v3;
                    if (!hi) { v0 = d[mi][ni][0]; v1 = d[mi][ni][1]; v2 = r0; v3 = r1; }
                    else     { v0 = r0; v1 = r1; v2 = d[mi][ni][2]; v3 = d[mi][ni][3]; }
                    if (drow >= 0) {
                        float* p = g_out + (size_t)drow * DD + ocb4 + ni * 8;
                        asm volatile("red.global.add.v4.f32 [%0], {%1,%2,%3,%4};"
                                     :: "l"(p), "f"(v0), "f"(v1), "f"(v2), "f"(v3) : "memory");
                    }
                }
            }
            __syncthreads();
        }
    }
}

// ---------------------------------------------------------------------------
// Fully fused MLP with cross-phase weight prefetch (unchanged from R14).
constexpr int MA_ATILE = 64 * DD;
constexpr int MA_BSTG  = 16384;
constexpr int MA_BOFF  = MA_ATILE;
constexpr int MA_HOFF  = MA_ATILE + 2 * MA_BSTG;
constexpr int MA_SMEM  = (MA_HOFF + 64 * H) * 2;   // 114688

__global__ void __launch_bounds__(256, 2) mlp_all(const float* __restrict__ In,
                                                  const __half* __restrict__ W1t,
                                                  const float* __restrict__ b1,
                                                  const __half* __restrict__ W2t,
                                                  const float* __restrict__ b2,
                                                  const __half* __restrict__ W3t,
                                                  const float* __restrict__ b3,
                                                  float* __restrict__ Out,
                                                  int Nrows) {
    extern __shared__ char smc[];
    __half* Atile = (__half*)smc;
    __half* Bbuf  = Atile + MA_BOFF;
    __half* Htile = Atile + MA_HOFF;
    int tid = threadIdx.x, lane = tid & 31, w = tid >> 5;
    int row0 = blockIdx.x * 64;

    if (blockIdx.x < NRL && tid == 0) g_fill[blockIdx.x] = 0;

    auto issueB1 = [&](int s, int buf) {
        uint32_t bbase = smem_u32(Bbuf + buf * MA_BSTG);
        int k0 = s * 64;
#pragma unroll
        for (int i = 0; i < 8; i++) {
            int l = tid + i * 256;
            int r = l >> 3, u = l & 7;
            const __half* src = W1t + (size_t)r * DD + k0 + u * 8;
            uint32_t dst = bbase + (uint32_t)((r * 8 + (u ^ (r & 7))) * 16);
            asm volatile("cp.async.ca.shared.global [%0], [%1], 16, %2;"
                         :: "r"(dst), "l"(src), "r"(16));
        }
    };
    auto issueB2 = [&](int s, int buf) {
        uint32_t bbase = smem_u32(Bbuf + buf * MA_BSTG);
        int k0 = s * 64;
#pragma unroll
        for (int i = 0; i < 8; i++) {
            int l = tid + i * 256;
            int r = l >> 3, u = l & 7;
            const __half* src = W2t + (size_t)r * H + k0 + u * 8;
            uint32_t dst = bbase + (uint32_t)((r * 8 + (u ^ (r & 7))) * 16);
            asm volatile("cp.async.ca.shared.global [%0], [%1], 16, %2;"
                         :: "r"(dst), "l"(src), "r"(16));
        }
    };
    auto issueB3 = [&](int s, int buf) {
        uint32_t bbase = smem_u32(Bbuf + buf * MA_BSTG);
        int k0 = s * 64;
#pragma unroll
        for (int i = 0; i < 4; i++) {
            int l = tid + i * 256;
            int r = l >> 3, u = l & 7;
            const __half* src = W3t + (size_t)r * H + k0 + u * 8;
            uint32_t dst = bbase + (uint32_t)((r * 8 + (u ^ (r & 7))) * 16);
            asm volatile("cp.async.ca.shared.global [%0], [%1], 16, %2;"
                         :: "r"(dst), "l"(src), "r"(16));
        }
    };

    issueB1(0, 0);
    asm volatile("cp.async.commit_group;");
    issueB1(1, 1);
    asm volatile("cp.async.commit_group;");

#pragma unroll
    for (int i = 0; i < 4; i++) {
        int l = tid + i * 256;
        int r = l >> 4, u = l & 15;
        int gr = row0 + r;
        float f[8];
        if (gr < Nrows) {
            const float4* src = (const float4*)(In + (size_t)gr * DD + u * 8);
            float4 a = src[0], b = src[1];
            f[0]=a.x; f[1]=a.y; f[2]=a.z; f[3]=a.w;
            f[4]=b.x; f[5]=b.y; f[6]=b.z; f[7]=b.w;
        } else {
#pragma unroll
            for (int q = 0; q < 8; q++) f[q] = 0.f;
        }
        uint32_t h[4];
        pack8h(h, f);
        *(uint4*)(Atile + (r * 16 + (u ^ (r & 7))) * 8) = make_uint4(h[0], h[1], h[2], h[3]);
    }

    int wm = w & 1, wn = w >> 1;
    int arow0 = wm * 32 + (lane & 15);
    int brow0 = wn * 64 + (lane & 15);
    uint32_t atile32 = smem_u32(Atile);
    uint32_t htile32 = smem_u32(Htile);

    float d[2][8][4];
#pragma unroll
    for (int mi = 0; mi < 2; mi++)
#pragma unroll
        for (int nj = 0; nj < 8; nj++)
#pragma unroll
            for (int c = 0; c < 4; c++) d[mi][nj][c] = 0.f;

    // ---- Phase 1: GEMM1 (64x256, K=128). W2-s0 prefetched during s=1. ----
    for (int s = 0; s < 2; s++) {
        if (s == 1) { issueB2(0, 0); asm volatile("cp.async.commit_group;"); }
        asm volatile("cp.async.wait_group 1;");
        __syncthreads();
        uint32_t bbase = smem_u32(Bbuf + (s & 1) * MA_BSTG);
#pragma unroll
        for (int ks = 0; ks < 4; ks++) {
            int uu = ks * 2 + (lane >> 4);
            int uua = s * 8 + uu;
            uint32_t a[2][4], b[4][4];
#pragma unroll
            for (int mi = 0; mi < 2; mi++) {
                int r = arow0 + mi * 16;
                ldsm4(a[mi], atile32 + (uint32_t)((r * 16 + (uua ^ (r & 7))) * 16));
            }
#pragma unroll
            for (int pp = 0; pp < 4; pp++) {
                int r = brow0 + pp * 16;
                ldsm4(b[pp], bbase + (uint32_t)((r * 8 + (uu ^ (r & 7))) * 16));
            }
#pragma unroll
            for (int mi = 0; mi < 2; mi++)
#pragma unroll
                for (int nj = 0; nj < 8; nj++) {
                    int pp = nj >> 1, o = nj & 1;
                    mma16(d[mi][nj], a[mi], b[pp][o], b[pp][2 + o]);
                }
        }
        __syncthreads();
    }

    // epilogue1: bias1+relu -> Htile
#pragma unroll
    for (int nj = 0; nj < 8; nj++) {
        int c = wn * 64 + nj * 8 + (lane & 3) * 2;
        float bj0 = b1[c], bj1 = b1[c + 1];
        int u = c >> 3, io = c & 7;
#pragma unroll
        for (int mi = 0; mi < 2; mi++) {
            int r = wm * 32 + mi * 16 + (lane >> 2);
            float v0 = fmaxf(d[mi][nj][0] + bj0, 0.f), v1 = fmaxf(d[mi][nj][1] + bj1, 0.f);
            float v2 = fmaxf(d[mi][nj][2] + bj0, 0.f), v3 = fmaxf(d[mi][nj][3] + bj1, 0.f);
            __half2 h0 = __floats2half2_rn(v0, v1);
            __half2 h1 = __floats2half2_rn(v2, v3);
            *(__half2*)&Htile[(size_t)r * 256 + ((u ^ (r & 7)) << 3) + io] = h0;
            int r1 = r + 8;
            *(__half2*)&Htile[(size_t)r1 * 256 + ((u ^ (r1 & 7)) << 3) + io] = h1;
        }
    }
    __syncthreads();

    // ---- Phase 2: GEMM2 (64x256, K=256). W3-s0 prefetched during s=3. ----
#pragma unroll
    for (int mi = 0; mi < 2; mi++)
#pragma unroll
        for (int nj = 0; nj < 8; nj++)
#pragma unroll
            for (int c = 0; c < 4; c++) d[mi][nj][c] = 0.f;

    for (int s = 0; s < 4; s++) {
        if (s + 1 < 4) {
            issueB2(s + 1, (s + 1) & 1);
            asm volatile("cp.async.commit_group;");
            asm volatile("cp.async.wait_group 1;");
        } else {
            issueB3(0, 0);
            asm volatile("cp.async.commit_group;");
            asm volatile("cp.async.wait_group 1;");
        }
        __syncthreads();
        uint32_t bbase = smem_u32(Bbuf + (s & 1) * MA_BSTG);
#pragma unroll
        for (int ks = 0; ks < 4; ks++) {
            int uu = ks * 2 + (lane >> 4);
            int uua = s * 8 + uu;
            uint32_t a[2][4], b[4][4];
#pragma unroll
            for (int mi = 0; mi < 2; mi++) {
                int r = arow0 + mi * 16;
                ldsm4(a[mi], htile32 + (uint32_t)((r * 32 + (uua ^ (r & 7))) * 16));
            }
#pragma unroll
            for (int pp = 0; pp < 4; pp++) {
                int r = brow0 + pp * 16;
                ldsm4(b[pp], bbase + (uint32_t)((r * 8 + (uu ^ (r & 7))) * 16));
            }
#pragma unroll
            for (int mi = 0; mi < 2; mi++)
#pragma unroll
                for (int nj = 0; nj < 8; nj++) {
                    int pp = nj >> 1, o = nj & 1;
                    mma16(d[mi][nj], a[mi], b[pp][o], b[pp][2 + o]);
                }
        }
        __syncthreads();
    }

    // epilogue2: bias2+relu -> Htile overwrite
#pragma unroll
    for (int nj = 0; nj < 8; nj++) {
        int c = wn * 64 + nj * 8 + (lane & 3) * 2;
        float bj0 = b2[c], bj1 = b2[c + 1];
        int u = c >> 3, io = c & 7;
#pragma unroll
        for (int mi = 0; mi < 2; mi++) {
            int r = wm * 32 + mi * 16 + (lane >> 2);
            float v0 = fmaxf(d[mi][nj][0] + bj0, 0.f), v1 = fmaxf(d[mi][nj][1] + bj1, 0.f);
            float v2 = fmaxf(d[mi][nj][2] + bj0, 0.f), v3 = fmaxf(d[mi][nj][3] + bj1, 0.f);
            __half2 h0 = __floats2half2_rn(v0, v1);
            __half2 h1 = __floats2half2_rn(v2, v3);
            *(__half2*)&Htile[(size_t)r * 256 + ((u ^ (r & 7)) << 3) + io] = h0;
            int r1 = r + 8;
            *(__half2*)&Htile[(size_t)r1 * 256 + ((u ^ (r1 & 7)) << 3) + io] = h1;
        }
    }
    __syncthreads();

    // ---- Phase 3: GEMM3 (64x128, K=256) ----
    int brow3 = wn * 32 + (lane & 15);
    float d3[2][4][4];
#pragma unroll
    for (int mi = 0; mi < 2; mi++)
#pragma unroll
        for (int ni = 0; ni < 4; ni++)
#pragma unroll
            for (int c = 0; c < 4; c++) d3[mi][ni][c] = 0.f;

    for (int s = 0; s < 4; s++) {
        if (s + 1 < 4) {
            issueB3(s + 1, (s + 1) & 1);
            asm volatile("cp.async.commit_group;");
            asm volatile("cp.async.wait_group 1;");
        } else {
            asm volatile("cp.async.wait_group 0;");
        }
        __syncthreads();
        uint32_t bbase = smem_u32(Bbuf + (s & 1) * MA_BSTG);
#pragma unroll
        for (int ks = 0; ks < 4; ks++) {
            int uu = ks * 2 + (lane >> 4);
            int uua = s * 8 + uu;
            uint32_t a[2][4], b[2][4];
#pragma unroll
            for (int mi = 0; mi < 2; mi++) {
                int r = arow0 + mi * 16;
                ldsm4(a[mi], htile32 + (uint32_t)((r * 32 + (uua ^ (r & 7))) * 16));
            }
#pragma unroll
            for (int pp = 0; pp < 2; pp++) {
                int r = brow3 + pp * 16;
                ldsm4(b[pp], bbase + (uint32_t)((r * 8 + (uu ^ (r & 7))) * 16));
            }
#pragma unroll
            for (int mi = 0; mi < 2; mi++)
#pragma unroll
                for (int ni = 0; ni < 4; ni++) {
                    int pp = ni >> 1, o = ni & 1;
                    mma16(d3[mi][ni], a[mi], b[pp][o], b[pp][2 + o]);
                }
        }
        __syncthreads();
    }

    // epilogue3: bias3, fp32 stores
#pragma unroll
    for (int ni = 0; ni < 4; ni++) {
        int gc = wn * 32 + ni * 8 + (lane & 3) * 2;
        float bj0 = b3[gc], bj1 = b3[gc + 1];
#pragma unroll
        for (int mi = 0; mi < 2; mi++) {
            int gr = row0 + wm * 32 + mi * 16 + (lane >> 2);
            float v0 = d3[mi][ni][0] + bj0, v1 = d3[mi][ni][1] + bj1;
            float v2 = d3[mi][ni][2] + bj0, v3 = d3[mi][ni][3] + bj1;
            if (gr < Nrows)     *(float2*)&Out[(size_t)gr * DD + gc]       = make_float2(v0, v1);
            if (gr + 8 < Nrows) *(float2*)&Out[(size_t)(gr + 8) * DD + gc] = make_float2(v2, v3);
        }
    }
}

// ---------------------------------------------------------------------------
extern "C" void kernel_launch(void* const* d_in, const int* in_sizes, int n_in,
                              void* d_out, int out_size) {
    const float* x     = (const float*)d_in[0];
    const int*   ei    = (const int*)d_in[1];
    const int*   et    = (const int*)d_in[2];
    const float* W     = (const float*)d_in[3];
    const float* eps   = (const float*)d_in[4];
    const float* A_emb = (const float*)d_in[5];
    const float* B_emb = (const float*)d_in[6];
    const float* W1    = (const float*)d_in[7];
    const float* b1    = (const float*)d_in[8];
    const float* W2    = (const float*)d_in[9];
    const float* b2    = (const float*)d_in[10];
    const float* W3    = (const float*)d_in[11];
    const float* b3    = (const float*)d_in[12];
    float* out = (float*)d_out;

    void *p_out, *p_xh, *p_w1, *p_w2, *p_w3;
    cudaGetSymbolAddress(&p_out, g_out);
    cudaGetSymbolAddress(&p_xh, g_xh);
    cudaGetSymbolAddress(&p_w1, g_W1h);
    cudaGetSymbolAddress(&p_w2, g_W2h);
    cudaGetSymbolAddress(&p_w3, g_W3h);

    cudaFuncSetAttribute(k_edge_mma, cudaFuncAttributeMaxDynamicSharedMemorySize, EDGE_SMEM);
    cudaFuncSetAttribute(mlp_all, cudaFuncAttributeMaxDynamicSharedMemorySize, MA_SMEM);

    k_prep<<<PREP_GRID, 256>>>(x, eps, W, A_emb, B_emb, W1, W2, W3, et);   // 0
    k_edge_mma<<<EDGE_GRID, 256, EDGE_SMEM>>>((const __half*)p_xh, ei);    // 1

    int gm = (NND + 63) / 64;   // 1563
    mlp_all<<<gm, 256, MA_SMEM>>>((const float*)p_out, (const __half*)p_w1, b1,
                                  (const __half*)p_w2, b2, (const __half*)p_w3, b3,
                                  out, NND);                               // 2
}

// round 16
// speedup vs baseline: 1.0085x; 1.0085x over previous
#include <cuda_runtime.h>
#include <cuda_fp16.h>
#include <cstdint>

constexpr int NND = 100000;
constexpr int DD  = 128;
constexpr int EE  = 250000;
constexpr int NRL = 16;
constexpr int RR  = 8;
constexpr int H   = 256;
constexpr int TE  = 64;
constexpr int CHUNK = 16;
constexpr int EDGE_GRID = 444;

// Static device scratch
__device__ __half g_Mh[NRL * DD * DD];
__device__ float  g_out[(size_t)NND * DD];
__device__ __half g_xh[(size_t)NND * DD];
__device__ __half g_W1h[H * DD];
__device__ __half g_W2h[H * H];
__device__ __half g_W3h[DD * H];
__device__ int    g_eidsb[(size_t)NRL * EE];
__device__ int    g_fill[NRL];

// ---------------------------------------------------------------------------
__device__ __forceinline__ uint32_t smem_u32(const void* p) {
    return (uint32_t)__cvta_generic_to_shared(p);
}
__device__ __forceinline__ void ldsm4(uint32_t* r, uint32_t addr) {
    asm volatile("ldmatrix.sync.aligned.m8n8.x4.shared.b16 {%0,%1,%2,%3}, [%4];"
                 : "=r"(r[0]), "=r"(r[1]), "=r"(r[2]), "=r"(r[3]) : "r"(addr));
}
__device__ __forceinline__ void mma16(float* d, const uint32_t* a, uint32_t b0, uint32_t b1) {
    asm volatile(
        "mma.sync.aligned.m16n8k16.row.col.f32.f16.f16.f32 "
        "{%0,%1,%2,%3},{%4,%5,%6,%7},{%8,%9},{%0,%1,%2,%3};"
        : "+f"(d[0]), "+f"(d[1]), "+f"(d[2]), "+f"(d[3])
        : "r"(a[0]), "r"(a[1]), "r"(a[2]), "r"(a[3]), "r"(b0), "r"(b1));
}
__device__ __forceinline__ void pack8h(uint32_t* o, const float* f) {
#pragma unroll
    for (int i = 0; i < 4; i++) {
        __half2 h = __floats2half2_rn(f[2 * i], f[2 * i + 1]);
        o[i] = *(uint32_t*)&h;
    }
}

// ---------------------------------------------------------------------------
// Fused prep, reordered so atomic/odd work launches FIRST and hides under the
// long copy wave: scatter | build_M | cvt_w | init_out+cvt_x (1 float4/thr).
constexpr int PREP_BM0   = 977;                       // scatter: [0,977)
constexpr int PREP_CVTW0 = PREP_BM0 + NRL;            // 993
constexpr int PREP_CPY0  = PREP_CVTW0 + 256;          // 1249
constexpr int PREP_GRID  = PREP_CPY0 + 12500;         // 13749

__global__ void __launch_bounds__(256) k_prep(const float* __restrict__ x,
                                              const float* __restrict__ eps,
                                              const float* __restrict__ W,
                                              const float* __restrict__ A_emb,
                                              const float* __restrict__ B_emb,
                                              const float* __restrict__ W1,
                                              const float* __restrict__ W2,
                                              const float* __restrict__ W3,
                                              const int* __restrict__ et) {
    int b = blockIdx.x;
    if (b < PREP_BM0) {
        // bucketed edge scatter (atomic-heavy; launch first)
        __shared__ int lc[NRL], lbase[NRL], lfill[NRL];
        if (threadIdx.x < NRL) { lc[threadIdx.x] = 0; lfill[threadIdx.x] = 0; }
        __syncthreads();
        int e = b * 256 + threadIdx.x;
        int t = -1;
        if (e < EE) {
            t = et[e];
            if (t >= 0 && t < NRL) atomicAdd(&lc[t], 1); else t = -1;
        }
        __syncthreads();
        if (threadIdx.x < NRL && lc[threadIdx.x])
            lbase[threadIdx.x] = atomicAdd(&g_fill[threadIdx.x], lc[threadIdx.x]);
        __syncthreads();
        if (t >= 0) {
            int p = atomicAdd(&lfill[t], 1);
            g_eidsb[(size_t)t * EE + lbase[t] + p] = e;
        }
    } else if (b < PREP_CVTW0) {
        // build fused relation matrix, fp16
        int t = b - PREP_BM0;
        __shared__ float As[DD * RR];
        __shared__ float Bs[DD * RR];
        for (int i = threadIdx.x; i < DD * RR; i += blockDim.x) {
            As[i] = A_emb[(size_t)t * DD * RR + i];
            Bs[i] = B_emb[(size_t)t * DD * RR + i];
        }
        __syncthreads();
        for (int idx = threadIdx.x; idx < DD * DD; idx += blockDim.x) {
            int o = idx >> 7;
            int i = idx & 127;
            float s = W[o * DD + i];
#pragma unroll
            for (int k = 0; k < RR; k++) s += Bs[i * RR + k] * As[o * RR + k];
            g_Mh[t * DD * DD + o * DD + i] = __float2half_rn(s);
        }
    } else if (b < PREP_CPY0) {
        int i = (b - PREP_CVTW0) * 256 + threadIdx.x;
        if (i < H * DD) g_W1h[i] = __float2half_rn(W1[i]);
        if (i < H * H)  g_W2h[i] = __float2half_rn(W2[i]);
        if (i < DD * H) g_W3h[i] = __float2half_rn(W3[i]);
    } else {
        // read x once -> g_out = (1+eps)*x AND g_xh = fp16(x)
        float s = 1.0f + eps[0];
        int i = (b - PREP_CPY0) * 256 + threadIdx.x;
        if (i < NND * DD / 4) {
            float4 v = ((const float4*)x)[i];
            __half2 h0 = __floats2half2_rn(v.x, v.y);
            __half2 h1 = __floats2half2_rn(v.z, v.w);
            uint2 u; u.x = *(uint32_t*)&h0; u.y = *(uint32_t*)&h1;
            ((uint2*)g_xh)[i] = u;
            v.x *= s; v.y *= s; v.z *= s; v.w *= s;
            ((float4*)g_out)[i] = v;
        }
    }
}

// ---------------------------------------------------------------------------
// Persistent edge GEMM; scatter via lane-paired red.v4. (unchanged from R14)
constexpr int EDGE_SMEM = 32768 + 32768 + CHUNK * TE * 2 * 4;

__global__ void __launch_bounds__(256, 3) k_edge_mma(const __half* __restrict__ xh,
                                                     const int* __restrict__ ei) {
    extern __shared__ char smc[];
    __half* Ms = (__half*)smc;
    char* Xb = smc + 32768;
    int* srcsA = (int*)(smc + 65536);
    int* dstsA = srcsA + CHUNK * TE;
    __shared__ int s_cnt[NRL];
    __shared__ int s_tstart[NRL + 1];
    __shared__ int s_trel[CHUNK];
    int tid = threadIdx.x;

    if (tid < NRL) s_cnt[tid] = g_fill[tid];
    __syncthreads();
    if (tid == 0) {
        int tb = 0;
        for (int t = 0; t < NRL; t++) { s_tstart[t] = tb; tb += (s_cnt[t] + TE - 1) / TE; }
        s_tstart[NRL] = tb;
    }
    __syncthreads();
    int nt = s_tstart[NRL];

    int per = (nt + gridDim.x - 1) / gridDim.x;
    int i0 = blockIdx.x * per;
    int i1 = min(i0 + per, nt);
    if (i0 >= i1) return;

    int lane = tid & 31, w = tid >> 5;
    int wm = w & 1, wn = w >> 1;
    int arow0 = wm * 32 + (lane & 15);
    int brow0 = wn * 32 + (lane & 15);
    uint32_t ms_base = smem_u32(Ms);
    int cur_rel = -1;
    int hi = lane & 1;
    int ocb4 = wn * 32 + ((lane & 3) >> 1) * 4;

    auto gather = [&](int k) {
        char* xb = Xb + (k & 1) * 16384;
        const int* sp = srcsA + k * TE;
        uint32_t xb32 = smem_u32(xb);
#pragma unroll
        for (int i = 0; i < 4; i++) {
            int l = tid + i * 256;
            int r = l >> 4, u = l & 15;
            int s = sp[r];
            bool pa = s >= 0;
            const __half* src = pa ? (xh + (size_t)s * DD + u * 8) : xh;
            uint32_t dst = xb32 + (uint32_t)((r * 16 + (u ^ (r & 7))) * 16);
            asm volatile("cp.async.ca.shared.global [%0], [%1], 16, %2;"
                         :: "r"(dst), "l"(src), "r"(pa ? 16 : 0));
        }
        asm volatile("cp.async.commit_group;");
    };

    for (int gbase = i0; gbase < i1; gbase += CHUNK) {
        int gc = min(CHUNK, i1 - gbase);

        if (tid < gc) {
            int ti = gbase + tid;
            int t = 0;
            for (int tt = 0; tt < NRL; tt++)
                if (ti >= s_tstart[tt] && ti < s_tstart[tt + 1]) t = tt;
            s_trel[tid] = t;
        }
        __syncthreads();

        for (int l = tid; l < gc * TE; l += 256) {
            int k = l >> 6, j = l & 63;
            int t = s_trel[k];
            int row0 = (gbase + k - s_tstart[t]) * TE;
            int cnt = s_cnt[t] - row0;
            int s = -1, d = -1;
            if (j < cnt) {
                int e = g_eidsb[(size_t)t * EE + row0 + j];
                s = ei[e];
                d = ei[EE + e];
                if (s < 0 || s >= NND) s = -1;
                if (d < 0 || d >= NND) d = -1;
            }
            srcsA[l] = s;
            dstsA[l] = d;
        }
        __syncthreads();

        gather(0);
        for (int k = 0; k < gc; k++) {
            if (k + 1 < gc) {
                gather(k + 1);
                asm volatile("cp.async.wait_group 1;");
            } else {
                asm volatile("cp.async.wait_group 0;");
            }
            __syncthreads();

            int t = s_trel[k];
            if (t != cur_rel) {
                const uint4* Msrc = (const uint4*)(g_Mh + (size_t)t * DD * DD);
#pragma unroll
                for (int j = 0; j < 8; j++) {
                    int l = tid + j * 256;
                    int r = l >> 4, u = l & 15;
                    uint4 v = Msrc[l];
                    *(uint4*)((char*)Ms + (r * 16 + (u ^ (r & 7))) * 16) = v;
                }
                cur_rel = t;
                __syncthreads();
            }

            uint32_t xs_base = smem_u32(Xb + (k & 1) * 16384);
            float d[2][4][4];
#pragma unroll
            for (int mi = 0; mi < 2; mi++)
#pragma unroll
                for (int ni = 0; ni < 4; ni++)
#pragma unroll
                    for (int c = 0; c < 4; c++) d[mi][ni][c] = 0.f;

#pragma unroll
            for (int ks = 0; ks < 8; ks++) {
                int uu = ks * 2 + (lane >> 4);
                uint32_t a[2][4], b[2][4];
#pragma unroll
                for (int mi = 0; mi < 2; mi++) {
                    int r = arow0 + mi * 16;
                    ldsm4(a[mi], xs_base + (uint32_t)((r * 16 + (uu ^ (r & 7))) * 16));
                }
#pragma unroll
                for (int pp = 0; pp < 2; pp++) {
                    int r = brow0 + pp * 16;
                    ldsm4(b[pp], ms_base + (uint32_t)((r * 16 + (uu ^ (r & 7))) * 16));
                }
#pragma unroll
                for (int mi = 0; mi < 2; mi++)
#pragma unroll
                    for (int ni = 0; ni < 4; ni++) {
                        int pp = ni >> 1, o = ni & 1;
                        mma16(d[mi][ni], a[mi], b[pp][o], b[pp][2 + o]);
                    }
            }

            const int* dp = dstsA + k * TE;
#pragma unroll
            for (int mi = 0; mi < 2; mi++) {
                int er = wm * 32 + mi * 16 + (lane >> 2);
                int drow = hi ? dp[er + 8] : dp[er];
#pragma unroll
                for (int ni = 0; ni < 4; ni++) {
                    float s0 = hi ? d[mi][ni][0] : d[mi][ni][2];
                    float s1 = hi ? d[mi][ni][1] : d[mi][ni][3];
                    float r0 = __shfl_xor_sync(0xffffffffu, s0, 1);
                    float r1 = __shfl_xor_sync(0xffffffffu, s1, 1);
                    float v0, v1, v2, v3;
                    if (!hi) { v0 = d[mi][ni][0]; v1 = d[mi][ni][1]; v2 = r0; v3 = r1; }
                    else     { v0 = r0; v1 = r1; v2 = d[mi][ni][2]; v3 = d[mi][ni][3]; }
                    if (drow >= 0) {
                        float* p = g_out + (size_t)drow * DD + ocb4 + ni * 8;
                        asm volatile("red.global.add.v4.f32 [%0], {%1,%2,%3,%4};"
                                     :: "l"(p), "f"(v0), "f"(v1), "f"(v2), "f"(v3) : "memory");
                    }
                }
            }
            __syncthreads();
        }
    }
}

// ---------------------------------------------------------------------------
// Fully fused MLP with cross-phase weight prefetch (unchanged from R14).
constexpr int MA_ATILE = 64 * DD;
constexpr int MA_BSTG  = 16384;
constexpr int MA_BOFF  = MA_ATILE;
constexpr int MA_HOFF  = MA_ATILE + 2 * MA_BSTG;
constexpr int MA_SMEM  = (MA_HOFF + 64 * H) * 2;   // 114688

__global__ void __launch_bounds__(256, 2) mlp_all(const float* __restrict__ In,
                                                  const __half* __restrict__ W1t,
                                                  const float* __restrict__ b1,
                                                  const __half* __restrict__ W2t,
                                                  const float* __restrict__ b2,
                                                  const __half* __restrict__ W3t,
                                                  const float* __restrict__ b3,
                                                  float* __restrict__ Out,
                                                  int Nrows) {
    extern __shared__ char smc[];
    __half* Atile = (__half*)smc;
    __half* Bbuf  = Atile + MA_BOFF;
    __half* Htile = Atile + MA_HOFF;
    int tid = threadIdx.x, lane = tid & 31, w = tid >> 5;
    int row0 = blockIdx.x * 64;

    if (blockIdx.x < NRL && tid == 0) g_fill[blockIdx.x] = 0;

    auto issueB1 = [&](int s, int buf) {
        uint32_t bbase = smem_u32(Bbuf + buf * MA_BSTG);
        int k0 = s * 64;
#pragma unroll
        for (int i = 0; i < 8; i++) {
            int l = tid + i * 256;
            int r = l >> 3, u = l & 7;
            const __half* src = W1t + (size_t)r * DD + k0 + u * 8;
            uint32_t dst = bbase + (uint32_t)((r * 8 + (u ^ (r & 7))) * 16);
            asm volatile("cp.async.ca.shared.global [%0], [%1], 16, %2;"
                         :: "r"(dst), "l"(src), "r"(16));
        }
    };
    auto issueB2 = [&](int s, int buf) {
        uint32_t bbase = smem_u32(Bbuf + buf * MA_BSTG);
        int k0 = s * 64;
#pragma unroll
        for (int i = 0; i < 8; i++) {
            int l = tid + i * 256;
            int r = l >> 3, u = l & 7;
            const __half* src = W2t + (size_t)r * H + k0 + u * 8;
            uint32_t dst = bbase + (uint32_t)((r * 8 + (u ^ (r & 7))) * 16);
            asm volatile("cp.async.ca.shared.global [%0], [%1], 16, %2;"
                         :: "r"(dst), "l"(src), "r"(16));
        }
    };
    auto issueB3 = [&](int s, int buf) {
        uint32_t bbase = smem_u32(Bbuf + buf * MA_BSTG);
        int k0 = s * 64;
#pragma unroll
        for (int i = 0; i < 4; i++) {
            int l = tid + i * 256;
            int r = l >> 3, u = l & 7;
            const __half* src = W3t + (size_t)r * H + k0 + u * 8;
            uint32_t dst = bbase + (uint32_t)((r * 8 + (u ^ (r & 7))) * 16);
            asm volatile("cp.async.ca.shared.global [%0], [%1], 16, %2;"
                         :: "r"(dst), "l"(src), "r"(16));
        }
    };

    issueB1(0, 0);
    asm volatile("cp.async.commit_group;");
    issueB1(1, 1);
    asm volatile("cp.async.commit_group;");

#pragma unroll
    for (int i = 0; i < 4; i++) {
        int l = tid + i * 256;
        int r = l >> 4, u = l & 15;
        int gr = row0 + r;
        float f[8];
        if (gr < Nrows) {
            const float4* src = (const float4*)(In + (size_t)gr * DD + u * 8);
            float4 a = src[0], b = src[1];
            f[0]=a.x; f[1]=a.y; f[2]=a.z; f[3]=a.w;
            f[4]=b.x; f[5]=b.y; f[6]=b.z; f[7]=b.w;
        } else {
#pragma unroll
            for (int q = 0; q < 8; q++) f[q] = 0.f;
        }
        uint32_t h[4];
        pack8h(h, f);
        *(uint4*)(Atile + (r * 16 + (u ^ (r & 7))) * 8) = make_uint4(h[0], h[1], h[2], h[3]);
    }

    int wm = w & 1, wn = w >> 1;
    int arow0 = wm * 32 + (lane & 15);
    int brow0 = wn * 64 + (lane & 15);
    uint32_t atile32 = smem_u32(Atile);
    uint32_t htile32 = smem_u32(Htile);

    float d[2][8][4];
#pragma unroll
    for (int mi = 0; mi < 2; mi++)
#pragma unroll
        for (int nj = 0; nj < 8; nj++)
#pragma unroll
            for (int c = 0; c < 4; c++) d[mi][nj][c] = 0.f;

    // ---- Phase 1: GEMM1 (64x256, K=128). W2-s0 prefetched during s=1. ----
    for (int s = 0; s < 2; s++) {
        if (s == 1) { issueB2(0, 0); asm volatile("cp.async.commit_group;"); }
        asm volatile("cp.async.wait_group 1;");
        __syncthreads();
        uint32_t bbase = smem_u32(Bbuf + (s & 1) * MA_BSTG);
#pragma unroll
        for (int ks = 0; ks < 4; ks++) {
            int uu = ks * 2 + (lane >> 4);
            int uua = s * 8 + uu;
            uint32_t a[2][4], b[4][4];
#pragma unroll
            for (int mi = 0; mi < 2; mi++) {
                int r = arow0 + mi * 16;
                ldsm4(a[mi], atile32 + (uint32_t)((r * 16 + (uua ^ (r & 7))) * 16));
            }
#pragma unroll
            for (int pp = 0; pp < 4; pp++) {
                int r = brow0 + pp * 16;
                ldsm4(b[pp], bbase + (uint32_t)((r * 8 + (uu ^ (r & 7))) * 16));
            }
#pragma unroll
            for (int mi = 0; mi < 2; mi++)
#pragma unroll
                for (int nj = 0; nj < 8; nj++) {
                    int pp = nj >> 1, o = nj & 1;
                    mma16(d[mi][nj], a[mi], b[pp][o], b[pp][2 + o]);
                }
        }
        __syncthreads();
    }

    // epilogue1: bias1+relu -> Htile
#pragma unroll
    for (int nj = 0; nj < 8; nj++) {
        int c = wn * 64 + nj * 8 + (lane & 3) * 2;
        float bj0 = b1[c], bj1 = b1[c + 1];
        int u = c >> 3, io = c & 7;
#pragma unroll
        for (int mi = 0; mi < 2; mi++) {
            int r = wm * 32 + mi * 16 + (lane >> 2);
            float v0 = fmaxf(d[mi][nj][0] + bj0, 0.f), v1 = fmaxf(d[mi][nj][1] + bj1, 0.f);
            float v2 = fmaxf(d[mi][nj][2] + bj0, 0.f), v3 = fmaxf(d[mi][nj][3] + bj1, 0.f);
            __half2 h0 = __floats2half2_rn(v0, v1);
            __half2 h1 = __floats2half2_rn(v2, v3);
            *(__half2*)&Htile[(size_t)r * 256 + ((u ^ (r & 7)) << 3) + io] = h0;
            int r1 = r + 8;
            *(__half2*)&Htile[(size_t)r1 * 256 + ((u ^ (r1 & 7)) << 3) + io] = h1;
        }
    }
    __syncthreads();

    // ---- Phase 2: GEMM2 (64x256, K=256). W3-s0 prefetched during s=3. ----
#pragma unroll
    for (int mi = 0; mi < 2; mi++)
#pragma unroll
        for (int nj = 0; nj < 8; nj++)
#pragma unroll
            for (int c = 0; c < 4; c++) d[mi][nj][c] = 0.f;

    for (int s = 0; s < 4; s++) {
        if (s + 1 < 4) {
            issueB2(s + 1, (s + 1) & 1);
            asm volatile("cp.async.commit_group;");
            asm volatile("cp.async.wait_group 1;");
        } else {
            issueB3(0, 0);
            asm volatile("cp.async.commit_group;");
            asm volatile("cp.async.wait_group 1;");
        }
        __syncthreads();
        uint32_t bbase = smem_u32(Bbuf + (s & 1) * MA_BSTG);
#pragma unroll
        for (int ks = 0; ks < 4; ks++) {
            int uu = ks * 2 + (lane >> 4);
            int uua = s * 8 + uu;
            uint32_t a[2][4], b[4][4];
#pragma unroll
            for (int mi = 0; mi < 2; mi++) {
                int r = arow0 + mi * 16;
                ldsm4(a[mi], htile32 + (uint32_t)((r * 32 + (uua ^ (r & 7))) * 16));
            }
#pragma unroll
            for (int pp = 0; pp < 4; pp++) {
                int r = brow0 + pp * 16;
                ldsm4(b[pp], bbase + (uint32_t)((r * 8 + (uu ^ (r & 7))) * 16));
            }
#pragma unroll
            for (int mi = 0; mi < 2; mi++)
#pragma unroll
                for (int nj = 0; nj < 8; nj++) {
                    int pp = nj >> 1, o = nj & 1;
                    mma16(d[mi][nj], a[mi], b[pp][o], b[pp][2 + o]);
                }
        }
        __syncthreads();
    }

    // epilogue2: bias2+relu -> Htile overwrite
#pragma unroll
    for (int nj = 0; nj < 8; nj++) {
        int c = wn * 64 + nj * 8 + (lane & 3) * 2;
        float bj0 = b2[c], bj1 = b2[c + 1];
        int u = c >> 3, io = c & 7;
#pragma unroll
        for (int mi = 0; mi < 2; mi++) {
            int r = wm * 32 + mi * 16 + (lane >> 2);
            float v0 = fmaxf(d[mi][nj][0] + bj0, 0.f), v1 = fmaxf(d[mi][nj][1] + bj1, 0.f);
            float v2 = fmaxf(d[mi][nj][2] + bj0, 0.f), v3 = fmaxf(d[mi][nj][3] + bj1, 0.f);
            __half2 h0 = __floats2half2_rn(v0, v1);
            __half2 h1 = __floats2half2_rn(v2, v3);
            *(__half2*)&Htile[(size_t)r * 256 + ((u ^ (r & 7)) << 3) + io] = h0;
            int r1 = r + 8;
            *(__half2*)&Htile[(size_t)r1 * 256 + ((u ^ (r1 & 7)) << 3) + io] = h1;
        }
    }
    __syncthreads();

    // ---- Phase 3: GEMM3 (64x128, K=256) ----
    int brow3 = wn * 32 + (lane & 15);
    float d3[2][4][4];
#pragma unroll
    for (int mi = 0; mi < 2; mi++)
#pragma unroll
        for (int ni = 0; ni < 4; ni++)
#pragma unroll
            for (int c = 0; c < 4; c++) d3[mi][ni][c] = 0.f;

    for (int s = 0; s < 4; s++) {
        if (s + 1 < 4) {
            issueB3(s + 1, (s + 1) & 1);
            asm volatile("cp.async.commit_group;");
            asm volatile("cp.async.wait_group 1;");
        } else {
            asm volatile("cp.async.wait_group 0;");
        }
        __syncthreads();
        uint32_t bbase = smem_u32(Bbuf + (s & 1) * MA_BSTG);
#pragma unroll
        for (int ks = 0; ks < 4; ks++) {
            int uu = ks * 2 + (lane >> 4);
            int uua = s * 8 + uu;
            uint32_t a[2][4], b[2][4];
#pragma unroll
            for (int mi = 0; mi < 2; mi++) {
                int r = arow0 + mi * 16;
                ldsm4(a[mi], htile32 + (uint32_t)((r * 32 + (uua ^ (r & 7))) * 16));
            }
#pragma unroll
            for (int pp = 0; pp < 2; pp++) {
                int r = brow3 + pp * 16;
                ldsm4(b[pp], bbase + (uint32_t)((r * 8 + (uu ^ (r & 7))) * 16));
            }
#pragma unroll
            for (int mi = 0; mi < 2; mi++)
#pragma unroll
                for (int ni = 0; ni < 4; ni++) {
                    int pp = ni >> 1, o = ni & 1;
                    mma16(d3[mi][ni], a[mi], b[pp][o], b[pp][2 + o]);
                }
        }
        __syncthreads();
    }

    // epilogue3: bias3, fp32 stores
#pragma unroll
    for (int ni = 0; ni < 4; ni++) {
        int gc = wn * 32 + ni * 8 + (lane & 3) * 2;
        float bj0 = b3[gc], bj1 = b3[gc + 1];
#pragma unroll
        for (int mi = 0; mi < 2; mi++) {
            int gr = row0 + wm * 32 + mi * 16 + (lane >> 2);
            float v0 = d3[mi][ni][0] + bj0, v1 = d3[mi][ni][1] + bj1;
            float v2 = d3[mi][ni][2] + bj0, v3 = d3[mi][ni][3] + bj1;
            if (gr < Nrows)     *(float2*)&Out[(size_t)gr * DD + gc]       = make_float2(v0, v1);
            if (gr + 8 < Nrows) *(float2*)&Out[(size_t)(gr + 8) * DD + gc] = make_float2(v2, v3);
        }
    }
}

// ---------------------------------------------------------------------------
extern "C" void kernel_launch(void* const* d_in, const int* in_sizes, int n_in,
                              void* d_out, int out_size) {
    const float* x     = (const float*)d_in[0];
    const int*   ei    = (const int*)d_in[1];
    const int*   et    = (const int*)d_in[2];
    const float* W     = (const float*)d_in[3];
    const float* eps   = (const float*)d_in[4];
    const float* A_emb = (const float*)d_in[5];
    const float* B_emb = (const float*)d_in[6];
    const float* W1    = (const float*)d_in[7];
    const float* b1    = (const float*)d_in[8];
    const float* W2    = (const float*)d_in[9];
    const float* b2    = (const float*)d_in[10];
    const float* W3    = (const float*)d_in[11];
    const float* b3    = (const float*)d_in[12];
    float* out = (float*)d_out;

    void *p_out, *p_xh, *p_w1, *p_w2, *p_w3;
    cudaGetSymbolAddress(&p_out, g_out);
    cudaGetSymbolAddress(&p_xh, g_xh);
    cudaGetSymbolAddress(&p_w1, g_W1h);
    cudaGetSymbolAddress(&p_w2, g_W2h);
    cudaGetSymbolAddress(&p_w3, g_W3h);

    cudaFuncSetAttribute(k_edge_mma, cudaFuncAttributeMaxDynamicSharedMemorySize, EDGE_SMEM);
    cudaFuncSetAttribute(mlp_all, cudaFuncAttributeMaxDynamicSharedMemorySize, MA_SMEM);

    k_prep<<<PREP_GRID, 256>>>(x, eps, W, A_emb, B_emb, W1, W2, W3, et);   // 0
    k_edge_mma<<<EDGE_GRID, 256, EDGE_SMEM>>>((const __half*)p_xh, ei);    // 1

    int gm = (NND + 63) / 64;   // 1563
    mlp_all<<<gm, 256, MA_SMEM>>>((const float*)p_out, (const __half*)p_w1, b1,
                                  (const __half*)p_w2, b2, (const __half*)p_w3, b3,
                                  out, NND);                               // 2
}